// round 7
// baseline (speedup 1.0000x reference)
#include <cuda_runtime.h>
#include <cuda_bf16.h>
#include <math.h>
#include <cstdint>

#define S_DIM 128
#define R_DIM 256
#define CS 256
#define CH 32
#define CZ 128
#define MDIM 8192           // R_DIM * CH
#define LN_EPS 1e-5f
#define MASK_EPS 1e-3f

// Scratch (static __device__ arrays — no cudaMalloc allowed)
__device__ __nv_bfloat16 g_ah[MDIM * S_DIM];        // A hi, K-major [m][s]
__device__ __nv_bfloat16 g_al[MDIM * S_DIM];        // A lo
__device__ __nv_bfloat16 g_bh[MDIM * S_DIM];        // B hi
__device__ __nv_bfloat16 g_bl[MDIM * S_DIM];        // B lo
__device__ __nv_bfloat16 g_wh[CZ * 1024];           // w_out^T hi [z][k]
__device__ __nv_bfloat16 g_wl[CZ * 1024];           // w_out^T lo

// ---------------- helpers ---------------------------------------------------
__device__ __forceinline__ void mma_bf16(float* c, const uint32_t* a, const uint32_t* b) {
    asm volatile(
        "mma.sync.aligned.m16n8k16.row.col.f32.bf16.bf16.f32 "
        "{%0,%1,%2,%3},{%4,%5,%6,%7},{%8,%9},{%0,%1,%2,%3};"
        : "+f"(c[0]), "+f"(c[1]), "+f"(c[2]), "+f"(c[3])
        : "r"(a[0]), "r"(a[1]), "r"(a[2]), "r"(a[3]), "r"(b[0]), "r"(b[1]));
}
__device__ __forceinline__ uint32_t pack_hi(float x, float y) {
    unsigned hx = __bfloat16_as_ushort(__float2bfloat16(x));
    unsigned hy = __bfloat16_as_ushort(__float2bfloat16(y));
    return hx | (hy << 16);
}
__device__ __forceinline__ uint32_t pack_lo(float x, float y) {
    float rx = x - __bfloat162float(__float2bfloat16(x));
    float ry = y - __bfloat162float(__float2bfloat16(y));
    unsigned lx = __bfloat16_as_ushort(__float2bfloat16(rx));
    unsigned ly = __bfloat16_as_ushort(__float2bfloat16(ry));
    return lx | (ly << 16);
}
__device__ __forceinline__ uint32_t smem_u32(const void* p) {
    uint32_t a;
    asm("{ .reg .u64 t; cvta.to.shared.u64 t, %1; cvt.u32.u64 %0, t; }"
        : "=r"(a) : "l"(p));
    return a;
}
__device__ __forceinline__ void cp16(uint32_t dst, const void* src) {
    asm volatile("cp.async.cg.shared.global [%0], [%1], 16;" :: "r"(dst), "l"(src));
}
#define CP_COMMIT() asm volatile("cp.async.commit_group;" ::: "memory")
#define CP_WAIT2()  asm volatile("cp.async.wait_group 2;" ::: "memory")

// stage-1 smem pipeline: K-chunk 16, 4 stages, 4 arrays of 128 rows x 48B.
#define RPAD 12
#define ROW_B 48
#define ARR_B   (128 * ROW_B)         // 6144 B per array
#define ST_B    (ARR_B * 4)           // 24576 B per stage
#define OFF_AH  0
#define OFF_AL  ARR_B
#define OFF_BH  (2 * ARR_B)
#define OFF_BL  (3 * ARR_B)
#define NSTAGE  4
#define SMEM_TOT (NSTAGE * ST_B)      // 98304 B (also covers stage-2 A2: 67072 B)

// stage-2 A2 layout: 16 rows x 524 u32 (stride 524 -> conflict-free frags)
#define A2_STRIDE 524
#define A2L_OFF   (16 * A2_STRIDE * 4)   // 33536 B

// ---------------------------------------------------------------------------
// Kernel 1: LayerNorm + dual projection -> K-major bf16 hi/lo tiles.
// ---------------------------------------------------------------------------
__global__ __launch_bounds__(256) void k_proj(
    const float* __restrict__ m, const float* __restrict__ mask,
    const float* __restrict__ lnw, const float* __restrict__ lnb,
    const float* __restrict__ w1, const float* __restrict__ b1,
    const float* __restrict__ w2, const float* __restrict__ b2)
{
    __shared__ float mhs[32][CS];     // 32 KB
    __shared__ float lnws[CS], lnbs[CS];

    int tid  = threadIdx.x;
    int lane = tid & 31;
    int wid  = tid >> 5;

    lnws[tid] = lnw[tid];
    lnbs[tid] = lnb[tid];
    __syncthreads();

    int r  = blockIdx.x & 255;
    int sg = blockIdx.x >> 8;      // 0..3

    #pragma unroll
    for (int rr = 0; rr < 4; rr++) {
        int rl  = wid * 4 + rr;            // 0..31
        int s   = sg * 32 + rl;
        int row = s * R_DIM + r;
        const float4* mrow = (const float4*)(m + (size_t)row * CS);
        float4 v0 = mrow[lane * 2];
        float4 v1 = mrow[lane * 2 + 1];
        float s1 = v0.x + v0.y + v0.z + v0.w + v1.x + v1.y + v1.z + v1.w;
        float s2 = v0.x*v0.x + v0.y*v0.y + v0.z*v0.z + v0.w*v0.w
                 + v1.x*v1.x + v1.y*v1.y + v1.z*v1.z + v1.w*v1.w;
        #pragma unroll
        for (int off = 16; off; off >>= 1) {
            s1 += __shfl_xor_sync(0xffffffffu, s1, off);
            s2 += __shfl_xor_sync(0xffffffffu, s2, off);
        }
        float mu   = s1 * (1.0f / CS);
        float var  = s2 * (1.0f / CS) - mu * mu;
        float rstd = rsqrtf(var + LN_EPS);
        int c0 = lane * 8;
        float t[8] = {v0.x, v0.y, v0.z, v0.w, v1.x, v1.y, v1.z, v1.w};
        #pragma unroll
        for (int q = 0; q < 8; q++) {
            int c = c0 + q;
            mhs[rl][c] = (t[q] - mu) * rstd * lnws[c] + lnbs[c];
        }
    }
    __syncthreads();

    int p  = tid & 31;                  // output-pair index
    int rg = tid >> 5;                  // 0..7 -> 4 s-rows each
    bool isA = (p < 16);
    int h0 = isA ? (2 * p) : (2 * (p - 16));
    const float* wb = isA ? w1 : w2;

    float acc[4][2];
    #pragma unroll
    for (int j = 0; j < 4; j++) { acc[j][0] = 0.f; acc[j][1] = 0.f; }

    #pragma unroll 4
    for (int c = 0; c < CS; c++) {
        float2 wv = *(const float2*)(wb + c * CH + h0);
        #pragma unroll
        for (int j = 0; j < 4; j++) {
            float mv = mhs[rg * 4 + j][c];
            acc[j][0] += mv * wv.x;
            acc[j][1] += mv * wv.y;
        }
    }

    float2 bias = *(const float2*)((isA ? b1 : b2) + h0);
    __nv_bfloat16* dh = isA ? g_ah : g_bh;
    __nv_bfloat16* dl = isA ? g_al : g_bl;
    int s0 = sg * 32 + rg * 4;

    float va[4], vb2[4];
    #pragma unroll
    for (int j = 0; j < 4; j++) {
        float mk = mask[(s0 + j) * R_DIM + r];
        va[j]  = (acc[j][0] + bias.x) * mk;
        vb2[j] = (acc[j][1] + bias.y) * mk;
    }
    size_t base0 = (size_t)(r * CH + h0) * S_DIM + s0;
    *(uint2*)&dh[base0]         = make_uint2(pack_hi(va[0], va[1]), pack_hi(va[2], va[3]));
    *(uint2*)&dl[base0]         = make_uint2(pack_lo(va[0], va[1]), pack_lo(va[2], va[3]));
    *(uint2*)&dh[base0 + S_DIM] = make_uint2(pack_hi(vb2[0], vb2[1]), pack_hi(vb2[2], vb2[3]));
    *(uint2*)&dl[base0 + S_DIM] = make_uint2(pack_lo(vb2[0], vb2[1]), pack_lo(vb2[2], vb2[3]));
}

// ---------------------------------------------------------------------------
// Kernel 1b: transpose+convert w_out [k][z] fp32 -> g_wh/g_wl [z][k] bf16
// ---------------------------------------------------------------------------
__global__ void k_wprep(const float* __restrict__ w_out)
{
    __shared__ float t[32][33];
    int tx = threadIdx.x, ty = threadIdx.y;
    int k0 = blockIdx.x * 32, z0 = blockIdx.y * 32;
    t[ty][tx] = w_out[(size_t)(k0 + ty) * CZ + z0 + tx];
    __syncthreads();
    float v = t[tx][ty];                       // = w_out[k0+tx][z0+ty]
    __nv_bfloat16 hb = __float2bfloat16(v);
    __nv_bfloat16 lb = __float2bfloat16(v - __bfloat162float(hb));
    g_wh[(size_t)(z0 + ty) * 1024 + k0 + tx] = hb;
    g_wl[(size_t)(z0 + ty) * 1024 + k0 + tx] = lb;
}

// ---------------------------------------------------------------------------
// One K-chunk (16 k) of bf16x3 HMMA on a 128x128 tile (stage 1).
// ---------------------------------------------------------------------------
__device__ __forceinline__ void mma_chunk16(
    const char* stage, int wm, int wn, int g, int tg, float acc[4][4][4])
{
    const uint32_t* sAh = (const uint32_t*)(stage + OFF_AH);
    const uint32_t* sAl = (const uint32_t*)(stage + OFF_AL);
    const uint32_t* sBh = (const uint32_t*)(stage + OFF_BH);
    const uint32_t* sBl = (const uint32_t*)(stage + OFF_BL);

    uint32_t ah[4][4], al[4][4], bh[4][2], bl[4][2];
    #pragma unroll
    for (int mt = 0; mt < 4; mt++) {
        int r0 = (wm * 64 + mt * 16 + g) * RPAD;
        ah[mt][0] = sAh[r0 + tg];
        ah[mt][1] = sAh[r0 + 8 * RPAD + tg];
        ah[mt][2] = sAh[r0 + tg + 4];
        ah[mt][3] = sAh[r0 + 8 * RPAD + tg + 4];
        al[mt][0] = sAl[r0 + tg];
        al[mt][1] = sAl[r0 + 8 * RPAD + tg];
        al[mt][2] = sAl[r0 + tg + 4];
        al[mt][3] = sAl[r0 + 8 * RPAD + tg + 4];
    }
    #pragma unroll
    for (int nt = 0; nt < 4; nt++) {
        int rn = (wn * 32 + nt * 8 + g) * RPAD;
        bh[nt][0] = sBh[rn + tg];
        bh[nt][1] = sBh[rn + tg + 4];
        bl[nt][0] = sBl[rn + tg];
        bl[nt][1] = sBl[rn + tg + 4];
    }
    #pragma unroll
    for (int mt = 0; mt < 4; mt++)
        #pragma unroll
        for (int nt = 0; nt < 4; nt++) {
            mma_bf16(acc[mt][nt], ah[mt], bh[nt]);
            mma_bf16(acc[mt][nt], ah[mt], bl[nt]);
            mma_bf16(acc[mt][nt], al[mt], bh[nt]);
        }
}

// ---------------------------------------------------------------------------
// FUSED kernel: stage 1 = outer contraction (128x128 tile via HMMA bf16x3);
// stage 2 = in-CTA output GEMM (16 pairs x 128 z x 1024 hk) + bias + norm.
// ---------------------------------------------------------------------------
__global__ __launch_bounds__(256, 2) void k_fused(
    const float* __restrict__ mask, const float* __restrict__ b_out,
    float* __restrict__ out)
{
    extern __shared__ char smem[];
    __shared__ float norms[16];
    uint32_t sb = smem_u32(smem);

    int tid = threadIdx.x, lane = tid & 31, warp = tid >> 5;
    int g = lane >> 2, tg = lane & 3;
    int wm = warp & 1, wn = warp >> 1;
    int m0 = blockIdx.x * 128, n0 = blockIdx.y * 128;
    int ib = m0 >> 5, jb = n0 >> 5;      // global i/j base (4 each)

    // mask norms for this CTA's 16 pairs
    if (tid < 16) {
        int ig = ib + (tid >> 2);
        int jg = jb + (tid & 3);
        float nacc = 0.f;
        #pragma unroll 4
        for (int s = 0; s < S_DIM; s++)
            nacc += mask[s * R_DIM + ig] * mask[s * R_DIM + jg];
        norms[tid] = nacc;
    }

    const uint4* pah = (const uint4*)g_ah;
    const uint4* pal = (const uint4*)g_al;
    const uint4* pbh = (const uint4*)g_bh;
    const uint4* pbl = (const uint4*)g_bl;

    int row  = tid >> 1;                // 0..127
    int half = tid & 1;
    uint32_t dro = (uint32_t)(row * ROW_B + half * 16);

    float acc[4][4][4];
    #pragma unroll
    for (int a = 0; a < 4; a++)
        #pragma unroll
        for (int b = 0; b < 4; b++)
            #pragma unroll
            for (int c = 0; c < 4; c++) acc[a][b][c] = 0.f;

    // ---- stage 1: prologue ----
    #pragma unroll
    for (int pc = 0; pc < NSTAGE - 1; pc++) {
        uint32_t so = sb + pc * ST_B + dro;
        size_t ga = (size_t)(m0 + row) * 16 + pc * 2 + half;
        size_t gb = (size_t)(n0 + row) * 16 + pc * 2 + half;
        cp16(so + OFF_AH, pah + ga);
        cp16(so + OFF_AL, pal + ga);
        cp16(so + OFF_BH, pbh + gb);
        cp16(so + OFF_BL, pbl + gb);
        CP_COMMIT();
    }

    #pragma unroll
    for (int kc = 0; kc < 8; kc++) {
        CP_WAIT2();
        __syncthreads();
        int kp = kc + NSTAGE - 1;
        if (kp < 8) {
            uint32_t so = sb + (kp & 3) * ST_B + dro;
            size_t ga = (size_t)(m0 + row) * 16 + kp * 2 + half;
            size_t gb = (size_t)(n0 + row) * 16 + kp * 2 + half;
            cp16(so + OFF_AH, pah + ga);
            cp16(so + OFF_AL, pal + ga);
            cp16(so + OFF_BH, pbh + gb);
            cp16(so + OFF_BL, pbl + gb);
        }
        CP_COMMIT();
        mma_chunk16(smem + (kc & 3) * ST_B, wm, wn, g, tg, acc);
    }
    __syncthreads();   // everyone done reading pipeline smem

    // ---- spill acc -> A2 smem (bf16 hi/lo), layout [p=16][hk=1024] ----
    uint32_t* A2h = (uint32_t*)smem;
    uint32_t* A2l = (uint32_t*)(smem + A2L_OFF);
    #pragma unroll
    for (int mt = 0; mt < 4; mt++) {
        #pragma unroll
        for (int hf = 0; hf < 2; hf++) {
            int mloc = wm * 64 + mt * 16 + g + hf * 8;
            int li = mloc >> 5, h = mloc & 31;
            #pragma unroll
            for (int nt = 0; nt < 4; nt++) {
                int nloc = wn * 32 + nt * 8 + 2 * tg;
                int lj = nloc >> 5, kk = nloc & 31;
                int p = li * 4 + lj;
                int hkp = h * 16 + (kk >> 1);      // u32 index within row
                float cx = acc[mt][nt][hf * 2 + 0];
                float cy = acc[mt][nt][hf * 2 + 1];
                A2h[p * A2_STRIDE + hkp] = pack_hi(cx, cy);
                A2l[p * A2_STRIDE + hkp] = pack_lo(cx, cy);
            }
        }
    }
    __syncthreads();

    // ---- stage 2: per-warp GEMM 16(p) x 16(z) x 1024(hk) ----
    int zb = warp * 16;
    const uint32_t* wh32 = (const uint32_t*)g_wh;
    const uint32_t* wl32 = (const uint32_t*)g_wl;

    float c2[2][4];
    #pragma unroll
    for (int nt = 0; nt < 2; nt++)
        #pragma unroll
        for (int c = 0; c < 4; c++) c2[nt][c] = 0.f;

    uint32_t bh[2][2][2], bl[2][2][2];   // [buf][ntile][reg]
    #pragma unroll
    for (int nt = 0; nt < 2; nt++) {
        size_t base = (size_t)(zb + nt * 8 + g) * 512 + tg;
        bh[0][nt][0] = __ldg(wh32 + base);
        bh[0][nt][1] = __ldg(wh32 + base + 4);
        bl[0][nt][0] = __ldg(wl32 + base);
        bl[0][nt][1] = __ldg(wl32 + base + 4);
    }

    #pragma unroll 2
    for (int ks = 0; ks < 64; ks++) {
        int cur = ks & 1, nxt = cur ^ 1;
        if (ks < 63) {
            #pragma unroll
            for (int nt = 0; nt < 2; nt++) {
                size_t base = (size_t)(zb + nt * 8 + g) * 512 + (ks + 1) * 8 + tg;
                bh[nxt][nt][0] = __ldg(wh32 + base);
                bh[nxt][nt][1] = __ldg(wh32 + base + 4);
                bl[nxt][nt][0] = __ldg(wl32 + base);
                bl[nxt][nt][1] = __ldg(wl32 + base + 4);
            }
        }
        uint32_t ah[4], al[4];
        int c0 = ks * 8 + tg;
        ah[0] = A2h[g * A2_STRIDE + c0];
        ah[1] = A2h[(g + 8) * A2_STRIDE + c0];
        ah[2] = A2h[g * A2_STRIDE + c0 + 4];
        ah[3] = A2h[(g + 8) * A2_STRIDE + c0 + 4];
        al[0] = A2l[g * A2_STRIDE + c0];
        al[1] = A2l[(g + 8) * A2_STRIDE + c0];
        al[2] = A2l[g * A2_STRIDE + c0 + 4];
        al[3] = A2l[(g + 8) * A2_STRIDE + c0 + 4];
        #pragma unroll
        for (int nt = 0; nt < 2; nt++) {
            mma_bf16(c2[nt], ah, bh[cur][nt]);
            mma_bf16(c2[nt], al, bh[cur][nt]);
            mma_bf16(c2[nt], ah, bl[cur][nt]);
        }
    }

    // ---- stage-2 epilogue: bias + mask-norm divide, fp32 out ----
    #pragma unroll
    for (int nt = 0; nt < 2; nt++) {
        int z = zb + nt * 8 + 2 * tg;
        float2 bz = *(const float2*)&b_out[z];
        #pragma unroll
        for (int hf = 0; hf < 2; hf++) {
            int p = g + hf * 8;
            int ig = ib + (p >> 2);
            int jg = jb + (p & 3);
            float inv = 1.0f / (MASK_EPS + norms[p]);
            float cx = (c2[nt][hf * 2 + 0] + bz.x) * inv;
            float cy = (c2[nt][hf * 2 + 1] + bz.y) * inv;
            *(float2*)&out[((size_t)ig * R_DIM + jg) * CZ + z] = make_float2(cx, cy);
        }
    }
}

// ---------------------------------------------------------------------------
extern "C" void kernel_launch(void* const* d_in, const int* in_sizes, int n_in,
                              void* d_out, int out_size)
{
    const float* m     = (const float*)d_in[0];
    const float* mask  = (const float*)d_in[1];
    const float* lnw   = (const float*)d_in[2];
    const float* lnb   = (const float*)d_in[3];
    const float* w1    = (const float*)d_in[4];
    const float* b1    = (const float*)d_in[5];
    const float* w2    = (const float*)d_in[6];
    const float* b2    = (const float*)d_in[7];
    const float* w_out = (const float*)d_in[8];
    const float* b_out = (const float*)d_in[9];
    float* out = (float*)d_out;

    static int attr_done = 0;
    if (!attr_done) {
        cudaFuncSetAttribute(k_fused,
            cudaFuncAttributeMaxDynamicSharedMemorySize, SMEM_TOT);
        attr_done = 1;
    }

    k_wprep<<<dim3(32, 4), dim3(32, 32)>>>(w_out);
    k_proj<<<1024, 256>>>(m, mask, lnw, lnb, w1, b1, w2, b2);
    k_fused<<<dim3(64, 64), 256, SMEM_TOT>>>(mask, b_out, out);
}

// round 8
// speedup vs baseline: 1.4638x; 1.4638x over previous
#include <cuda_runtime.h>
#include <cuda_bf16.h>
#include <math.h>
#include <cstdint>

#define S_DIM 128
#define R_DIM 256
#define CS 256
#define CH 32
#define CZ 128
#define MDIM 8192           // R_DIM * CH
#define LN_EPS 1e-5f
#define MASK_EPS 1e-3f

// Scratch (static __device__ arrays — no cudaMalloc allowed)
__device__ __nv_bfloat16 g_ah[MDIM * S_DIM];        // A hi, K-major [m][s]
__device__ __nv_bfloat16 g_al[MDIM * S_DIM];        // A lo
__device__ __nv_bfloat16 g_bh[MDIM * S_DIM];        // B hi
__device__ __nv_bfloat16 g_bl[MDIM * S_DIM];        // B lo
__device__ __nv_bfloat16 g_oh[(size_t)65536 * 1024];  // outer hi [p][hk]
__device__ __nv_bfloat16 g_ol[(size_t)65536 * 1024];  // outer lo
__device__ __nv_bfloat16 g_wh[CZ * 1024];           // w_out^T hi [z][k]
__device__ __nv_bfloat16 g_wl[CZ * 1024];           // w_out^T lo

// ---------------- helpers ---------------------------------------------------
__device__ __forceinline__ void mma_bf16(float* c, const uint32_t* a, const uint32_t* b) {
    asm volatile(
        "mma.sync.aligned.m16n8k16.row.col.f32.bf16.bf16.f32 "
        "{%0,%1,%2,%3},{%4,%5,%6,%7},{%8,%9},{%0,%1,%2,%3};"
        : "+f"(c[0]), "+f"(c[1]), "+f"(c[2]), "+f"(c[3])
        : "r"(a[0]), "r"(a[1]), "r"(a[2]), "r"(a[3]), "r"(b[0]), "r"(b[1]));
}
__device__ __forceinline__ void ldsm_x4(uint32_t* r, uint32_t addr) {
    asm volatile("ldmatrix.sync.aligned.m8n8.x4.shared.b16 {%0,%1,%2,%3}, [%4];"
        : "=r"(r[0]), "=r"(r[1]), "=r"(r[2]), "=r"(r[3]) : "r"(addr));
}
__device__ __forceinline__ uint32_t pack_hi(float x, float y) {
    unsigned hx = __bfloat16_as_ushort(__float2bfloat16(x));
    unsigned hy = __bfloat16_as_ushort(__float2bfloat16(y));
    return hx | (hy << 16);
}
__device__ __forceinline__ uint32_t pack_lo(float x, float y) {
    float rx = x - __bfloat162float(__float2bfloat16(x));
    float ry = y - __bfloat162float(__float2bfloat16(y));
    unsigned lx = __bfloat16_as_ushort(__float2bfloat16(rx));
    unsigned ly = __bfloat16_as_ushort(__float2bfloat16(ry));
    return lx | (ly << 16);
}
__device__ __forceinline__ uint32_t smem_u32(const void* p) {
    uint32_t a;
    asm("{ .reg .u64 t; cvta.to.shared.u64 t, %1; cvt.u32.u64 %0, t; }"
        : "=r"(a) : "l"(p));
    return a;
}
__device__ __forceinline__ void cp16(uint32_t dst, const void* src) {
    asm volatile("cp.async.cg.shared.global [%0], [%1], 16;" :: "r"(dst), "l"(src));
}
#define CP_COMMIT() asm volatile("cp.async.commit_group;" ::: "memory")
#define CP_WAIT2()  asm volatile("cp.async.wait_group 2;" ::: "memory")

// smem pipeline: K-chunk 16, 4 stages. Per stage: 4 arrays of 128 rows x 48B.
#define RPAD 12
#define ROW_B 48
#define ARR_B   (128 * ROW_B)         // 6144 B per array
#define ST_B    (ARR_B * 4)           // 24576 B per stage
#define OFF_AH  0
#define OFF_AL  ARR_B
#define OFF_BH  (2 * ARR_B)
#define OFF_BL  (3 * ARR_B)
#define NSTAGE  4
#define SMEM_PIPE (NSTAGE * ST_B)     // 98304 B

// ---------------------------------------------------------------------------
// Kernel 1: LayerNorm + dual projection -> K-major bf16 hi/lo tiles.
// ---------------------------------------------------------------------------
__global__ __launch_bounds__(256) void k_proj(
    const float* __restrict__ m, const float* __restrict__ mask,
    const float* __restrict__ lnw, const float* __restrict__ lnb,
    const float* __restrict__ w1, const float* __restrict__ b1,
    const float* __restrict__ w2, const float* __restrict__ b2)
{
    __shared__ float mhs[32][CS];     // 32 KB
    __shared__ float lnws[CS], lnbs[CS];

    int tid  = threadIdx.x;
    int lane = tid & 31;
    int wid  = tid >> 5;

    lnws[tid] = lnw[tid];
    lnbs[tid] = lnb[tid];
    __syncthreads();

    int r  = blockIdx.x & 255;
    int sg = blockIdx.x >> 8;      // 0..3

    #pragma unroll
    for (int rr = 0; rr < 4; rr++) {
        int rl  = wid * 4 + rr;            // 0..31
        int s   = sg * 32 + rl;
        int row = s * R_DIM + r;
        const float4* mrow = (const float4*)(m + (size_t)row * CS);
        float4 v0 = mrow[lane * 2];
        float4 v1 = mrow[lane * 2 + 1];
        float s1 = v0.x + v0.y + v0.z + v0.w + v1.x + v1.y + v1.z + v1.w;
        float s2 = v0.x*v0.x + v0.y*v0.y + v0.z*v0.z + v0.w*v0.w
                 + v1.x*v1.x + v1.y*v1.y + v1.z*v1.z + v1.w*v1.w;
        #pragma unroll
        for (int off = 16; off; off >>= 1) {
            s1 += __shfl_xor_sync(0xffffffffu, s1, off);
            s2 += __shfl_xor_sync(0xffffffffu, s2, off);
        }
        float mu   = s1 * (1.0f / CS);
        float var  = s2 * (1.0f / CS) - mu * mu;
        float rstd = rsqrtf(var + LN_EPS);
        int c0 = lane * 8;
        float t[8] = {v0.x, v0.y, v0.z, v0.w, v1.x, v1.y, v1.z, v1.w};
        #pragma unroll
        for (int q = 0; q < 8; q++) {
            int c = c0 + q;
            mhs[rl][c] = (t[q] - mu) * rstd * lnws[c] + lnbs[c];
        }
    }
    __syncthreads();

    int p  = tid & 31;                  // output-pair index
    int rg = tid >> 5;                  // 0..7 -> 4 s-rows each
    bool isA = (p < 16);
    int h0 = isA ? (2 * p) : (2 * (p - 16));
    const float* wb = isA ? w1 : w2;

    float acc[4][2];
    #pragma unroll
    for (int j = 0; j < 4; j++) { acc[j][0] = 0.f; acc[j][1] = 0.f; }

    #pragma unroll 4
    for (int c = 0; c < CS; c++) {
        float2 wv = *(const float2*)(wb + c * CH + h0);
        #pragma unroll
        for (int j = 0; j < 4; j++) {
            float mv = mhs[rg * 4 + j][c];
            acc[j][0] += mv * wv.x;
            acc[j][1] += mv * wv.y;
        }
    }

    float2 bias = *(const float2*)((isA ? b1 : b2) + h0);
    __nv_bfloat16* dh = isA ? g_ah : g_bh;
    __nv_bfloat16* dl = isA ? g_al : g_bl;
    int s0 = sg * 32 + rg * 4;

    float va[4], vb2[4];
    #pragma unroll
    for (int j = 0; j < 4; j++) {
        float mk = mask[(s0 + j) * R_DIM + r];
        va[j]  = (acc[j][0] + bias.x) * mk;
        vb2[j] = (acc[j][1] + bias.y) * mk;
    }
    size_t base0 = (size_t)(r * CH + h0) * S_DIM + s0;
    *(uint2*)&dh[base0]         = make_uint2(pack_hi(va[0], va[1]), pack_hi(va[2], va[3]));
    *(uint2*)&dl[base0]         = make_uint2(pack_lo(va[0], va[1]), pack_lo(va[2], va[3]));
    *(uint2*)&dh[base0 + S_DIM] = make_uint2(pack_hi(vb2[0], vb2[1]), pack_hi(vb2[2], vb2[3]));
    *(uint2*)&dl[base0 + S_DIM] = make_uint2(pack_lo(vb2[0], vb2[1]), pack_lo(vb2[2], vb2[3]));
}

// ---------------------------------------------------------------------------
// Kernel 1b: transpose+convert w_out [k][z] fp32 -> g_wh/g_wl [z][k] bf16
// ---------------------------------------------------------------------------
__global__ void k_wprep(const float* __restrict__ w_out)
{
    __shared__ float t[32][33];
    int tx = threadIdx.x, ty = threadIdx.y;
    int k0 = blockIdx.x * 32, z0 = blockIdx.y * 32;
    t[ty][tx] = w_out[(size_t)(k0 + ty) * CZ + z0 + tx];
    __syncthreads();
    float v = t[tx][ty];                       // = w_out[k0+tx][z0+ty]
    __nv_bfloat16 hb = __float2bfloat16(v);
    __nv_bfloat16 lb = __float2bfloat16(v - __bfloat162float(hb));
    g_wh[(size_t)(z0 + ty) * 1024 + k0 + tx] = hb;
    g_wl[(size_t)(z0 + ty) * 1024 + k0 + tx] = lb;
}

// ---------------------------------------------------------------------------
// One K-chunk (16 k) of bf16x3 HMMA on a 128x128 tile — ldmatrix fragment IO.
// stage_sb = smem u32 address of this stage's base.
// ---------------------------------------------------------------------------
__device__ __forceinline__ void mma_chunk16(
    uint32_t stage_sb, int wm, int wn, int lane, float acc[4][4][4])
{
    // ldmatrix address: lane l -> row (base + (l&15)), k-half (l>>4)
    uint32_t rsel = (uint32_t)(lane & 15) * ROW_B + (uint32_t)(lane >> 4) * 16;

    uint32_t ah[4][4], al[4][4];
    #pragma unroll
    for (int mt = 0; mt < 4; mt++) {
        uint32_t off = (uint32_t)(wm * 64 + mt * 16) * ROW_B + rsel;
        ldsm_x4(ah[mt], stage_sb + OFF_AH + off);
        ldsm_x4(al[mt], stage_sb + OFF_AL + off);
    }
    // B: one x4 covers two 8-row n-tiles (r0=nt0.k0, r1=nt1.k0, r2=nt0.k1, r3=nt1.k1)
    uint32_t bhm[2][4], blm[2][4];
    #pragma unroll
    for (int ntp = 0; ntp < 2; ntp++) {
        uint32_t off = (uint32_t)(wn * 32 + ntp * 16) * ROW_B + rsel;
        ldsm_x4(bhm[ntp], stage_sb + OFF_BH + off);
        ldsm_x4(blm[ntp], stage_sb + OFF_BL + off);
    }

    #pragma unroll
    for (int mt = 0; mt < 4; mt++)
        #pragma unroll
        for (int nt = 0; nt < 4; nt++) {
            int ntp = nt >> 1, q = nt & 1;
            uint32_t bh2[2] = { bhm[ntp][q], bhm[ntp][2 + q] };
            uint32_t bl2[2] = { blm[ntp][q], blm[ntp][2 + q] };
            mma_bf16(acc[mt][nt], ah[mt], bh2);
            mma_bf16(acc[mt][nt], ah[mt], bl2);
            mma_bf16(acc[mt][nt], al[mt], bh2);
        }
}

// ---------------------------------------------------------------------------
// Kernel 2: outer contraction via HMMA bf16x3, 4-stage cp.async pipeline.
// ---------------------------------------------------------------------------
__global__ __launch_bounds__(256, 2) void k_gemm1_mma()
{
    extern __shared__ char smem[];
    uint32_t sb = smem_u32(smem);

    int tid = threadIdx.x, lane = tid & 31, warp = tid >> 5;
    int g = lane >> 2, tg = lane & 3;
    int wm = warp & 1, wn = warp >> 1;
    int m0 = blockIdx.x * 128, n0 = blockIdx.y * 128;

    const uint4* pah = (const uint4*)g_ah;
    const uint4* pal = (const uint4*)g_al;
    const uint4* pbh = (const uint4*)g_bh;
    const uint4* pbl = (const uint4*)g_bl;

    int row  = tid >> 1;                // 0..127
    int half = tid & 1;                 // 16B half within 32B chunk-row
    uint32_t dro = (uint32_t)(row * ROW_B + half * 16);

    float acc[4][4][4];
    #pragma unroll
    for (int a = 0; a < 4; a++)
        #pragma unroll
        for (int b = 0; b < 4; b++)
            #pragma unroll
            for (int c = 0; c < 4; c++) acc[a][b][c] = 0.f;

    // prologue: prefetch chunks 0..2
    #pragma unroll
    for (int pc = 0; pc < NSTAGE - 1; pc++) {
        uint32_t so = sb + pc * ST_B + dro;
        size_t ga = (size_t)(m0 + row) * 16 + pc * 2 + half;
        size_t gb = (size_t)(n0 + row) * 16 + pc * 2 + half;
        cp16(so + OFF_AH, pah + ga);
        cp16(so + OFF_AL, pal + ga);
        cp16(so + OFF_BH, pbh + gb);
        cp16(so + OFF_BL, pbl + gb);
        CP_COMMIT();
    }

    #pragma unroll
    for (int kc = 0; kc < 8; kc++) {
        CP_WAIT2();
        __syncthreads();
        int kp = kc + NSTAGE - 1;
        if (kp < 8) {
            uint32_t so = sb + (kp & 3) * ST_B + dro;
            size_t ga = (size_t)(m0 + row) * 16 + kp * 2 + half;
            size_t gb = (size_t)(n0 + row) * 16 + kp * 2 + half;
            cp16(so + OFF_AH, pah + ga);
            cp16(so + OFF_AL, pal + ga);
            cp16(so + OFF_BH, pbh + gb);
            cp16(so + OFF_BL, pbl + gb);
        }
        CP_COMMIT();
        mma_chunk16(sb + (kc & 3) * ST_B, wm, wn, lane, acc);
    }

    // Epilogue: bf16 hi/lo into [i][j][h][kk]
    uint32_t* oh32 = (uint32_t*)g_oh;
    uint32_t* ol32 = (uint32_t*)g_ol;
    #pragma unroll
    for (int mt = 0; mt < 4; mt++) {
        int mbase = m0 + wm * 64 + mt * 16 + g;
        #pragma unroll
        for (int nt = 0; nt < 4; nt++) {
            int n  = n0 + wn * 32 + nt * 8 + 2 * tg;
            int j  = n >> 5, kk = n & 31;
            #pragma unroll
            for (int hf = 0; hf < 2; hf++) {
                int mm = mbase + hf * 8;
                int i  = mm >> 5, h = mm & 31;
                float cx = acc[mt][nt][hf * 2 + 0];
                float cy = acc[mt][nt][hf * 2 + 1];
                size_t idx = (size_t)(i * R_DIM + j) * 512 + h * 16 + (kk >> 1);
                oh32[idx] = pack_hi(cx, cy);
                ol32[idx] = pack_lo(cx, cy);
            }
        }
    }
}

// ---------------------------------------------------------------------------
// Kernel 3: output GEMM via HMMA bf16x3 + bias + mask-norm, 4-stage pipeline.
// ---------------------------------------------------------------------------
__global__ __launch_bounds__(256, 2) void k_gemm2_mma(
    const float* __restrict__ mask, const float* __restrict__ b_out,
    float* __restrict__ out)
{
    extern __shared__ char smem[];
    __shared__ float norms[128];
    uint32_t sb = smem_u32(smem);

    int tid = threadIdx.x, lane = tid & 31, warp = tid >> 5;
    int g = lane >> 2, tg = lane & 3;
    int wm = warp & 1, wn = warp >> 1;
    int p0 = blockIdx.x * 128;
    int i  = p0 >> 8;
    int j0 = p0 & 255;

    if (tid < 128) {
        float nacc = 0.f;
        #pragma unroll 4
        for (int s = 0; s < S_DIM; s++)
            nacc += mask[s * R_DIM + i] * mask[s * R_DIM + j0 + tid];
        norms[tid] = nacc;
    }

    const uint4* pah = (const uint4*)g_oh;
    const uint4* pal = (const uint4*)g_ol;
    const uint4* pbh = (const uint4*)g_wh;
    const uint4* pbl = (const uint4*)g_wl;

    int row  = tid >> 1;
    int half = tid & 1;
    uint32_t dro = (uint32_t)(row * ROW_B + half * 16);

    float acc[4][4][4];
    #pragma unroll
    for (int a = 0; a < 4; a++)
        #pragma unroll
        for (int b = 0; b < 4; b++)
            #pragma unroll
            for (int c = 0; c < 4; c++) acc[a][b][c] = 0.f;

    // prologue
    #pragma unroll
    for (int pc = 0; pc < NSTAGE - 1; pc++) {
        uint32_t so = sb + pc * ST_B + dro;
        size_t ga = (size_t)(p0 + row) * 128 + pc * 2 + half;
        size_t gb = (size_t)row * 128 + pc * 2 + half;
        cp16(so + OFF_AH, pah + ga);
        cp16(so + OFF_AL, pal + ga);
        cp16(so + OFF_BH, pbh + gb);
        cp16(so + OFF_BL, pbl + gb);
        CP_COMMIT();
    }

    for (int kc = 0; kc < 64; kc++) {
        CP_WAIT2();
        __syncthreads();
        int kp = kc + NSTAGE - 1;
        if (kp < 64) {
            uint32_t so = sb + (kp & 3) * ST_B + dro;
            size_t ga = (size_t)(p0 + row) * 128 + kp * 2 + half;
            size_t gb = (size_t)row * 128 + kp * 2 + half;
            cp16(so + OFF_AH, pah + ga);
            cp16(so + OFF_AL, pal + ga);
            cp16(so + OFF_BH, pbh + gb);
            cp16(so + OFF_BL, pbl + gb);
        }
        CP_COMMIT();
        mma_chunk16(sb + (kc & 3) * ST_B, wm, wn, lane, acc);
    }

    // Epilogue: bias + norm divide, fp32 out
    #pragma unroll
    for (int mt = 0; mt < 4; mt++) {
        int pl = wm * 64 + mt * 16 + g;
        #pragma unroll
        for (int nt = 0; nt < 4; nt++) {
            int z = wn * 32 + nt * 8 + 2 * tg;
            float2 bz = *(const float2*)&b_out[z];
            #pragma unroll
            for (int hf = 0; hf < 2; hf++) {
                int pp = pl + hf * 8;
                float inv = 1.0f / (MASK_EPS + norms[pp]);
                float cx = (acc[mt][nt][hf * 2 + 0] + bz.x) * inv;
                float cy = (acc[mt][nt][hf * 2 + 1] + bz.y) * inv;
                *(float2*)&out[(size_t)(p0 + pp) * CZ + z] = make_float2(cx, cy);
            }
        }
    }
}

// ---------------------------------------------------------------------------
extern "C" void kernel_launch(void* const* d_in, const int* in_sizes, int n_in,
                              void* d_out, int out_size)
{
    const float* m     = (const float*)d_in[0];
    const float* mask  = (const float*)d_in[1];
    const float* lnw   = (const float*)d_in[2];
    const float* lnb   = (const float*)d_in[3];
    const float* w1    = (const float*)d_in[4];
    const float* b1    = (const float*)d_in[5];
    const float* w2    = (const float*)d_in[6];
    const float* b2    = (const float*)d_in[7];
    const float* w_out = (const float*)d_in[8];
    const float* b_out = (const float*)d_in[9];
    float* out = (float*)d_out;

    static int attr_done = 0;
    if (!attr_done) {
        cudaFuncSetAttribute(k_gemm1_mma,
            cudaFuncAttributeMaxDynamicSharedMemorySize, SMEM_PIPE);
        cudaFuncSetAttribute(k_gemm2_mma,
            cudaFuncAttributeMaxDynamicSharedMemorySize, SMEM_PIPE);
        attr_done = 1;
    }

    k_wprep<<<dim3(32, 4), dim3(32, 32)>>>(w_out);
    k_proj<<<1024, 256>>>(m, mask, lnw, lnb, w1, b1, w2, b2);
    k_gemm1_mma<<<dim3(64, 64), 256, SMEM_PIPE>>>();
    k_gemm2_mma<<<512, 256, SMEM_PIPE>>>(mask, b_out, out);
}

// round 9
// speedup vs baseline: 1.5373x; 1.0502x over previous
#include <cuda_runtime.h>
#include <cuda_bf16.h>
#include <math.h>
#include <cstdint>

#define S_DIM 128
#define R_DIM 256
#define CS 256
#define CH 32
#define CZ 128
#define MDIM 8192           // R_DIM * CH
#define LN_EPS 1e-5f
#define MASK_EPS 1e-3f

// Scratch (static __device__ arrays — no cudaMalloc allowed)
__device__ __nv_bfloat16 g_ah[MDIM * S_DIM];        // A hi, K-major [m][s]
__device__ __nv_bfloat16 g_al[MDIM * S_DIM];        // A lo
__device__ __nv_bfloat16 g_bh[MDIM * S_DIM];        // B hi
__device__ __nv_bfloat16 g_bl[MDIM * S_DIM];        // B lo
__device__ __nv_bfloat16 g_oh[(size_t)65536 * 1024];  // outer hi [p][hk]
__device__ __nv_bfloat16 g_ol[(size_t)65536 * 1024];  // outer lo
__device__ __nv_bfloat16 g_wh[CZ * 1024];           // w_out^T hi [z][k]
__device__ __nv_bfloat16 g_wl[CZ * 1024];           // w_out^T lo

// ---------------- helpers ---------------------------------------------------
__device__ __forceinline__ void mma_bf16(float* c, const uint32_t* a, const uint32_t* b) {
    asm volatile(
        "mma.sync.aligned.m16n8k16.row.col.f32.bf16.bf16.f32 "
        "{%0,%1,%2,%3},{%4,%5,%6,%7},{%8,%9},{%0,%1,%2,%3};"
        : "+f"(c[0]), "+f"(c[1]), "+f"(c[2]), "+f"(c[3])
        : "r"(a[0]), "r"(a[1]), "r"(a[2]), "r"(a[3]), "r"(b[0]), "r"(b[1]));
}
__device__ __forceinline__ uint32_t pack_hi(float x, float y) {
    unsigned hx = __bfloat16_as_ushort(__float2bfloat16(x));
    unsigned hy = __bfloat16_as_ushort(__float2bfloat16(y));
    return hx | (hy << 16);
}
__device__ __forceinline__ uint32_t pack_lo(float x, float y) {
    float rx = x - __bfloat162float(__float2bfloat16(x));
    float ry = y - __bfloat162float(__float2bfloat16(y));
    unsigned lx = __bfloat16_as_ushort(__float2bfloat16(rx));
    unsigned ly = __bfloat16_as_ushort(__float2bfloat16(ry));
    return lx | (ly << 16);
}
__device__ __forceinline__ uint32_t smem_u32(const void* p) {
    uint32_t a;
    asm("{ .reg .u64 t; cvta.to.shared.u64 t, %1; cvt.u32.u64 %0, t; }"
        : "=r"(a) : "l"(p));
    return a;
}
__device__ __forceinline__ void cp16(uint32_t dst, const void* src) {
    asm volatile("cp.async.cg.shared.global [%0], [%1], 16;" :: "r"(dst), "l"(src));
}
#define CP_COMMIT() asm volatile("cp.async.commit_group;" ::: "memory")
#define CP_WAIT2()  asm volatile("cp.async.wait_group 2;" ::: "memory")

// smem pipeline: K-chunk 16, 4 stages. Per stage: 4 arrays of 128 rows x 48B.
#define RPAD 12
#define ROW_B 48
#define ARR_B   (128 * ROW_B)         // 6144 B per array
#define ST_B    (ARR_B * 4)           // 24576 B per stage
#define OFF_AH  0
#define OFF_AL  ARR_B
#define OFF_BH  (2 * ARR_B)
#define OFF_BL  (3 * ARR_B)
#define NSTAGE  4
#define SMEM_PIPE (NSTAGE * ST_B)     // 98304 B

// ---------------------------------------------------------------------------
// Kernel 1: LayerNorm + dual projection -> K-major bf16 hi/lo tiles.
// ---------------------------------------------------------------------------
__global__ __launch_bounds__(256) void k_proj(
    const float* __restrict__ m, const float* __restrict__ mask,
    const float* __restrict__ lnw, const float* __restrict__ lnb,
    const float* __restrict__ w1, const float* __restrict__ b1,
    const float* __restrict__ w2, const float* __restrict__ b2)
{
    __shared__ float mhs[32][CS];     // 32 KB
    __shared__ float lnws[CS], lnbs[CS];

    int tid  = threadIdx.x;
    int lane = tid & 31;
    int wid  = tid >> 5;

    lnws[tid] = lnw[tid];
    lnbs[tid] = lnb[tid];
    __syncthreads();

    int r  = blockIdx.x & 255;
    int sg = blockIdx.x >> 8;      // 0..3

    #pragma unroll
    for (int rr = 0; rr < 4; rr++) {
        int rl  = wid * 4 + rr;            // 0..31
        int s   = sg * 32 + rl;
        int row = s * R_DIM + r;
        const float4* mrow = (const float4*)(m + (size_t)row * CS);
        float4 v0 = mrow[lane * 2];
        float4 v1 = mrow[lane * 2 + 1];
        float s1 = v0.x + v0.y + v0.z + v0.w + v1.x + v1.y + v1.z + v1.w;
        float s2 = v0.x*v0.x + v0.y*v0.y + v0.z*v0.z + v0.w*v0.w
                 + v1.x*v1.x + v1.y*v1.y + v1.z*v1.z + v1.w*v1.w;
        #pragma unroll
        for (int off = 16; off; off >>= 1) {
            s1 += __shfl_xor_sync(0xffffffffu, s1, off);
            s2 += __shfl_xor_sync(0xffffffffu, s2, off);
        }
        float mu   = s1 * (1.0f / CS);
        float var  = s2 * (1.0f / CS) - mu * mu;
        float rstd = rsqrtf(var + LN_EPS);
        int c0 = lane * 8;
        float t[8] = {v0.x, v0.y, v0.z, v0.w, v1.x, v1.y, v1.z, v1.w};
        #pragma unroll
        for (int q = 0; q < 8; q++) {
            int c = c0 + q;
            mhs[rl][c] = (t[q] - mu) * rstd * lnws[c] + lnbs[c];
        }
    }
    __syncthreads();

    int p  = tid & 31;                  // output-pair index
    int rg = tid >> 5;                  // 0..7 -> 4 s-rows each
    bool isA = (p < 16);
    int h0 = isA ? (2 * p) : (2 * (p - 16));
    const float* wb = isA ? w1 : w2;

    float acc[4][2];
    #pragma unroll
    for (int j = 0; j < 4; j++) { acc[j][0] = 0.f; acc[j][1] = 0.f; }

    #pragma unroll 4
    for (int c = 0; c < CS; c++) {
        float2 wv = *(const float2*)(wb + c * CH + h0);
        #pragma unroll
        for (int j = 0; j < 4; j++) {
            float mv = mhs[rg * 4 + j][c];
            acc[j][0] += mv * wv.x;
            acc[j][1] += mv * wv.y;
        }
    }

    float2 bias = *(const float2*)((isA ? b1 : b2) + h0);
    __nv_bfloat16* dh = isA ? g_ah : g_bh;
    __nv_bfloat16* dl = isA ? g_al : g_bl;
    int s0 = sg * 32 + rg * 4;

    float va[4], vb2[4];
    #pragma unroll
    for (int j = 0; j < 4; j++) {
        float mk = mask[(s0 + j) * R_DIM + r];
        va[j]  = (acc[j][0] + bias.x) * mk;
        vb2[j] = (acc[j][1] + bias.y) * mk;
    }
    size_t base0 = (size_t)(r * CH + h0) * S_DIM + s0;
    *(uint2*)&dh[base0]         = make_uint2(pack_hi(va[0], va[1]), pack_hi(va[2], va[3]));
    *(uint2*)&dl[base0]         = make_uint2(pack_lo(va[0], va[1]), pack_lo(va[2], va[3]));
    *(uint2*)&dh[base0 + S_DIM] = make_uint2(pack_hi(vb2[0], vb2[1]), pack_hi(vb2[2], vb2[3]));
    *(uint2*)&dl[base0 + S_DIM] = make_uint2(pack_lo(vb2[0], vb2[1]), pack_lo(vb2[2], vb2[3]));
}

// ---------------------------------------------------------------------------
// Kernel 1b: transpose+convert w_out [k][z] fp32 -> g_wh/g_wl [z][k] bf16
// ---------------------------------------------------------------------------
__global__ void k_wprep(const float* __restrict__ w_out)
{
    __shared__ float t[32][33];
    int tx = threadIdx.x, ty = threadIdx.y;
    int k0 = blockIdx.x * 32, z0 = blockIdx.y * 32;
    t[ty][tx] = w_out[(size_t)(k0 + ty) * CZ + z0 + tx];
    __syncthreads();
    float v = t[tx][ty];                       // = w_out[k0+tx][z0+ty]
    __nv_bfloat16 hb = __float2bfloat16(v);
    __nv_bfloat16 lb = __float2bfloat16(v - __bfloat162float(hb));
    g_wh[(size_t)(z0 + ty) * 1024 + k0 + tx] = hb;
    g_wl[(size_t)(z0 + ty) * 1024 + k0 + tx] = lb;
}

// ---------------------------------------------------------------------------
// One K-chunk (16 k) of bf16x3 HMMA on a 128x128 tile.
// MMA issue order: 3 independent sweeps (hh, hl, lh) over 16 accumulators —
// no back-to-back RAW on any accumulator.
// ---------------------------------------------------------------------------
__device__ __forceinline__ void mma_chunk16(
    const char* stage, int wm, int wn, int g, int tg, float acc[4][4][4])
{
    const uint32_t* sAh = (const uint32_t*)(stage + OFF_AH);
    const uint32_t* sAl = (const uint32_t*)(stage + OFF_AL);
    const uint32_t* sBh = (const uint32_t*)(stage + OFF_BH);
    const uint32_t* sBl = (const uint32_t*)(stage + OFF_BL);

    uint32_t ah[4][4], al[4][4], bh[4][2], bl[4][2];
    #pragma unroll
    for (int mt = 0; mt < 4; mt++) {
        int r0 = (wm * 64 + mt * 16 + g) * RPAD;
        ah[mt][0] = sAh[r0 + tg];
        ah[mt][1] = sAh[r0 + 8 * RPAD + tg];
        ah[mt][2] = sAh[r0 + tg + 4];
        ah[mt][3] = sAh[r0 + 8 * RPAD + tg + 4];
        al[mt][0] = sAl[r0 + tg];
        al[mt][1] = sAl[r0 + 8 * RPAD + tg];
        al[mt][2] = sAl[r0 + tg + 4];
        al[mt][3] = sAl[r0 + 8 * RPAD + tg + 4];
    }
    #pragma unroll
    for (int nt = 0; nt < 4; nt++) {
        int rn = (wn * 32 + nt * 8 + g) * RPAD;
        bh[nt][0] = sBh[rn + tg];
        bh[nt][1] = sBh[rn + tg + 4];
        bl[nt][0] = sBl[rn + tg];
        bl[nt][1] = sBl[rn + tg + 4];
    }
    // pass 1: Ah*Bh — 16 independent accumulators
    #pragma unroll
    for (int mt = 0; mt < 4; mt++)
        #pragma unroll
        for (int nt = 0; nt < 4; nt++)
            mma_bf16(acc[mt][nt], ah[mt], bh[nt]);
    // pass 2: Ah*Bl
    #pragma unroll
    for (int mt = 0; mt < 4; mt++)
        #pragma unroll
        for (int nt = 0; nt < 4; nt++)
            mma_bf16(acc[mt][nt], ah[mt], bl[nt]);
    // pass 3: Al*Bh
    #pragma unroll
    for (int mt = 0; mt < 4; mt++)
        #pragma unroll
        for (int nt = 0; nt < 4; nt++)
            mma_bf16(acc[mt][nt], al[mt], bh[nt]);
}

// ---------------------------------------------------------------------------
// Kernel 2: outer contraction via HMMA bf16x3, 4-stage cp.async pipeline.
// ---------------------------------------------------------------------------
__global__ __launch_bounds__(256, 2) void k_gemm1_mma()
{
    extern __shared__ char smem[];
    uint32_t sb = smem_u32(smem);

    int tid = threadIdx.x, lane = tid & 31, warp = tid >> 5;
    int g = lane >> 2, tg = lane & 3;
    int wm = warp & 1, wn = warp >> 1;
    int m0 = blockIdx.x * 128, n0 = blockIdx.y * 128;

    const uint4* pah = (const uint4*)g_ah;
    const uint4* pal = (const uint4*)g_al;
    const uint4* pbh = (const uint4*)g_bh;
    const uint4* pbl = (const uint4*)g_bl;

    int row  = tid >> 1;                // 0..127
    int half = tid & 1;                 // 16B half within 32B chunk-row
    uint32_t dro = (uint32_t)(row * ROW_B + half * 16);

    float acc[4][4][4];
    #pragma unroll
    for (int a = 0; a < 4; a++)
        #pragma unroll
        for (int b = 0; b < 4; b++)
            #pragma unroll
            for (int c = 0; c < 4; c++) acc[a][b][c] = 0.f;

    // prologue: prefetch chunks 0..2
    #pragma unroll
    for (int pc = 0; pc < NSTAGE - 1; pc++) {
        uint32_t so = sb + pc * ST_B + dro;
        size_t ga = (size_t)(m0 + row) * 16 + pc * 2 + half;
        size_t gb = (size_t)(n0 + row) * 16 + pc * 2 + half;
        cp16(so + OFF_AH, pah + ga);
        cp16(so + OFF_AL, pal + ga);
        cp16(so + OFF_BH, pbh + gb);
        cp16(so + OFF_BL, pbl + gb);
        CP_COMMIT();
    }

    #pragma unroll
    for (int kc = 0; kc < 8; kc++) {
        CP_WAIT2();
        __syncthreads();
        int kp = kc + NSTAGE - 1;
        if (kp < 8) {
            uint32_t so = sb + (kp & 3) * ST_B + dro;
            size_t ga = (size_t)(m0 + row) * 16 + kp * 2 + half;
            size_t gb = (size_t)(n0 + row) * 16 + kp * 2 + half;
            cp16(so + OFF_AH, pah + ga);
            cp16(so + OFF_AL, pal + ga);
            cp16(so + OFF_BH, pbh + gb);
            cp16(so + OFF_BL, pbl + gb);
        }
        CP_COMMIT();
        mma_chunk16(smem + (kc & 3) * ST_B, wm, wn, g, tg, acc);
    }

    // Epilogue: bf16 hi/lo into [i][j][h][kk]
    uint32_t* oh32 = (uint32_t*)g_oh;
    uint32_t* ol32 = (uint32_t*)g_ol;
    #pragma unroll
    for (int mt = 0; mt < 4; mt++) {
        int mbase = m0 + wm * 64 + mt * 16 + g;
        #pragma unroll
        for (int nt = 0; nt < 4; nt++) {
            int n  = n0 + wn * 32 + nt * 8 + 2 * tg;
            int j  = n >> 5, kk = n & 31;
            #pragma unroll
            for (int hf = 0; hf < 2; hf++) {
                int mm = mbase + hf * 8;
                int i  = mm >> 5, h = mm & 31;
                float cx = acc[mt][nt][hf * 2 + 0];
                float cy = acc[mt][nt][hf * 2 + 1];
                size_t idx = (size_t)(i * R_DIM + j) * 512 + h * 16 + (kk >> 1);
                oh32[idx] = pack_hi(cx, cy);
                ol32[idx] = pack_lo(cx, cy);
            }
        }
    }
}

// ---------------------------------------------------------------------------
// Kernel 3: output GEMM via HMMA bf16x3 + bias + mask-norm, 4-stage pipeline.
// ---------------------------------------------------------------------------
__global__ __launch_bounds__(256, 2) void k_gemm2_mma(
    const float* __restrict__ mask, const float* __restrict__ b_out,
    float* __restrict__ out)
{
    extern __shared__ char smem[];
    __shared__ float norms[128];
    uint32_t sb = smem_u32(smem);

    int tid = threadIdx.x, lane = tid & 31, warp = tid >> 5;
    int g = lane >> 2, tg = lane & 3;
    int wm = warp & 1, wn = warp >> 1;
    int p0 = blockIdx.x * 128;
    int i  = p0 >> 8;
    int j0 = p0 & 255;

    if (tid < 128) {
        float nacc = 0.f;
        #pragma unroll 4
        for (int s = 0; s < S_DIM; s++)
            nacc += mask[s * R_DIM + i] * mask[s * R_DIM + j0 + tid];
        norms[tid] = nacc;
    }

    const uint4* pah = (const uint4*)g_oh;
    const uint4* pal = (const uint4*)g_ol;
    const uint4* pbh = (const uint4*)g_wh;
    const uint4* pbl = (const uint4*)g_wl;

    int row  = tid >> 1;
    int half = tid & 1;
    uint32_t dro = (uint32_t)(row * ROW_B + half * 16);

    float acc[4][4][4];
    #pragma unroll
    for (int a = 0; a < 4; a++)
        #pragma unroll
        for (int b = 0; b < 4; b++)
            #pragma unroll
            for (int c = 0; c < 4; c++) acc[a][b][c] = 0.f;

    // prologue
    #pragma unroll
    for (int pc = 0; pc < NSTAGE - 1; pc++) {
        uint32_t so = sb + pc * ST_B + dro;
        size_t ga = (size_t)(p0 + row) * 128 + pc * 2 + half;
        size_t gb = (size_t)row * 128 + pc * 2 + half;
        cp16(so + OFF_AH, pah + ga);
        cp16(so + OFF_AL, pal + ga);
        cp16(so + OFF_BH, pbh + gb);
        cp16(so + OFF_BL, pbl + gb);
        CP_COMMIT();
    }

    for (int kc = 0; kc < 64; kc++) {
        CP_WAIT2();
        __syncthreads();
        int kp = kc + NSTAGE - 1;
        if (kp < 64) {
            uint32_t so = sb + (kp & 3) * ST_B + dro;
            size_t ga = (size_t)(p0 + row) * 128 + kp * 2 + half;
            size_t gb = (size_t)row * 128 + kp * 2 + half;
            cp16(so + OFF_AH, pah + ga);
            cp16(so + OFF_AL, pal + ga);
            cp16(so + OFF_BH, pbh + gb);
            cp16(so + OFF_BL, pbl + gb);
        }
        CP_COMMIT();
        mma_chunk16(smem + (kc & 3) * ST_B, wm, wn, g, tg, acc);
    }

    // Epilogue: bias + norm divide, fp32 out
    #pragma unroll
    for (int mt = 0; mt < 4; mt++) {
        int pl = wm * 64 + mt * 16 + g;
        #pragma unroll
        for (int nt = 0; nt < 4; nt++) {
            int z = wn * 32 + nt * 8 + 2 * tg;
            float2 bz = *(const float2*)&b_out[z];
            #pragma unroll
            for (int hf = 0; hf < 2; hf++) {
                int pp = pl + hf * 8;
                float inv = 1.0f / (MASK_EPS + norms[pp]);
                float cx = (acc[mt][nt][hf * 2 + 0] + bz.x) * inv;
                float cy = (acc[mt][nt][hf * 2 + 1] + bz.y) * inv;
                *(float2*)&out[(size_t)(p0 + pp) * CZ + z] = make_float2(cx, cy);
            }
        }
    }
}

// ---------------------------------------------------------------------------
extern "C" void kernel_launch(void* const* d_in, const int* in_sizes, int n_in,
                              void* d_out, int out_size)
{
    const float* m     = (const float*)d_in[0];
    const float* mask  = (const float*)d_in[1];
    const float* lnw   = (const float*)d_in[2];
    const float* lnb   = (const float*)d_in[3];
    const float* w1    = (const float*)d_in[4];
    const float* b1    = (const float*)d_in[5];
    const float* w2    = (const float*)d_in[6];
    const float* b2    = (const float*)d_in[7];
    const float* w_out = (const float*)d_in[8];
    const float* b_out = (const float*)d_in[9];
    float* out = (float*)d_out;

    static int attr_done = 0;
    if (!attr_done) {
        cudaFuncSetAttribute(k_gemm1_mma,
            cudaFuncAttributeMaxDynamicSharedMemorySize, SMEM_PIPE);
        cudaFuncSetAttribute(k_gemm2_mma,
            cudaFuncAttributeMaxDynamicSharedMemorySize, SMEM_PIPE);
        attr_done = 1;
    }

    k_wprep<<<dim3(32, 4), dim3(32, 32)>>>(w_out);
    k_proj<<<1024, 256>>>(m, mask, lnw, lnb, w1, b1, w2, b2);
    k_gemm1_mma<<<dim3(64, 64), 256, SMEM_PIPE>>>();
    k_gemm2_mma<<<512, 256, SMEM_PIPE>>>(mask, b_out, out);
}

// round 10
// speedup vs baseline: 3.1330x; 2.0380x over previous
#include <cuda_runtime.h>
#include <cuda_fp16.h>
#include <math.h>
#include <cstdint>

#define S_DIM 128
#define R_DIM 256
#define CS 256
#define CH 32
#define CZ 128
#define MDIM 8192           // R_DIM * CH
#define LN_EPS 1e-5f
#define MASK_EPS 1e-3f

// Scratch (static __device__ arrays — no cudaMalloc allowed)
__device__ __half g_a[MDIM * S_DIM];                // A fp16, K-major [m][s], 2 MB
__device__ __half g_b[MDIM * S_DIM];                // B fp16
__device__ __half g_o[(size_t)65536 * 1024];        // outer fp16 [p][hk], 134 MB
__device__ __half g_w[CZ * 1024];                   // w_out^T fp16 [z][k]

// ---------------- helpers ---------------------------------------------------
__device__ __forceinline__ void mma_f16(float* c, const uint32_t* a, const uint32_t* b) {
    asm volatile(
        "mma.sync.aligned.m16n8k16.row.col.f32.f16.f16.f32 "
        "{%0,%1,%2,%3},{%4,%5,%6,%7},{%8,%9},{%0,%1,%2,%3};"
        : "+f"(c[0]), "+f"(c[1]), "+f"(c[2]), "+f"(c[3])
        : "r"(a[0]), "r"(a[1]), "r"(a[2]), "r"(a[3]), "r"(b[0]), "r"(b[1]));
}
__device__ __forceinline__ uint32_t pack_h2(float x, float y) {
    unsigned lx = __half_as_ushort(__float2half_rn(x));
    unsigned ly = __half_as_ushort(__float2half_rn(y));
    return lx | (ly << 16);
}
__device__ __forceinline__ uint32_t smem_u32(const void* p) {
    uint32_t a;
    asm("{ .reg .u64 t; cvta.to.shared.u64 t, %1; cvt.u32.u64 %0, t; }"
        : "=r"(a) : "l"(p));
    return a;
}
__device__ __forceinline__ void cp16(uint32_t dst, const void* src) {
    asm volatile("cp.async.cg.shared.global [%0], [%1], 16;" :: "r"(dst), "l"(src));
}
#define CP_COMMIT() asm volatile("cp.async.commit_group;" ::: "memory")
#define CP_WAIT2()  asm volatile("cp.async.wait_group 2;" ::: "memory")

// smem pipeline: K-chunk 32 (64B/row), 4 stages, 2 arrays of 128 rows x 80B.
#define RPAD 20               // u32 per row (64B data + 16B pad) -> conflict-free
#define ROW_B 80
#define ARR_B   (128 * ROW_B)         // 10240 B per array
#define ST_B    (ARR_B * 2)           // 20480 B per stage
#define OFF_A   0
#define OFF_B   ARR_B
#define NSTAGE  4
#define SMEM_PIPE (NSTAGE * ST_B)     // 81920 B

// ---------------------------------------------------------------------------
// Kernel 1: LayerNorm + dual projection -> K-major fp16 tiles.
// ---------------------------------------------------------------------------
__global__ __launch_bounds__(256) void k_proj(
    const float* __restrict__ m, const float* __restrict__ mask,
    const float* __restrict__ lnw, const float* __restrict__ lnb,
    const float* __restrict__ w1, const float* __restrict__ b1,
    const float* __restrict__ w2, const float* __restrict__ b2)
{
    __shared__ float mhs[32][CS];     // 32 KB
    __shared__ float lnws[CS], lnbs[CS];

    int tid  = threadIdx.x;
    int lane = tid & 31;
    int wid  = tid >> 5;

    lnws[tid] = lnw[tid];
    lnbs[tid] = lnb[tid];
    __syncthreads();

    int r  = blockIdx.x & 255;
    int sg = blockIdx.x >> 8;      // 0..3

    #pragma unroll
    for (int rr = 0; rr < 4; rr++) {
        int rl  = wid * 4 + rr;            // 0..31
        int s   = sg * 32 + rl;
        int row = s * R_DIM + r;
        const float4* mrow = (const float4*)(m + (size_t)row * CS);
        float4 v0 = mrow[lane * 2];
        float4 v1 = mrow[lane * 2 + 1];
        float s1 = v0.x + v0.y + v0.z + v0.w + v1.x + v1.y + v1.z + v1.w;
        float s2 = v0.x*v0.x + v0.y*v0.y + v0.z*v0.z + v0.w*v0.w
                 + v1.x*v1.x + v1.y*v1.y + v1.z*v1.z + v1.w*v1.w;
        #pragma unroll
        for (int off = 16; off; off >>= 1) {
            s1 += __shfl_xor_sync(0xffffffffu, s1, off);
            s2 += __shfl_xor_sync(0xffffffffu, s2, off);
        }
        float mu   = s1 * (1.0f / CS);
        float var  = s2 * (1.0f / CS) - mu * mu;
        float rstd = rsqrtf(var + LN_EPS);
        int c0 = lane * 8;
        float t[8] = {v0.x, v0.y, v0.z, v0.w, v1.x, v1.y, v1.z, v1.w};
        #pragma unroll
        for (int q = 0; q < 8; q++) {
            int c = c0 + q;
            mhs[rl][c] = (t[q] - mu) * rstd * lnws[c] + lnbs[c];
        }
    }
    __syncthreads();

    int p  = tid & 31;                  // output-pair index
    int rg = tid >> 5;                  // 0..7 -> 4 s-rows each
    bool isA = (p < 16);
    int h0 = isA ? (2 * p) : (2 * (p - 16));
    const float* wb = isA ? w1 : w2;

    float acc[4][2];
    #pragma unroll
    for (int j = 0; j < 4; j++) { acc[j][0] = 0.f; acc[j][1] = 0.f; }

    #pragma unroll 4
    for (int c = 0; c < CS; c++) {
        float2 wv = *(const float2*)(wb + c * CH + h0);
        #pragma unroll
        for (int j = 0; j < 4; j++) {
            float mv = mhs[rg * 4 + j][c];
            acc[j][0] += mv * wv.x;
            acc[j][1] += mv * wv.y;
        }
    }

    float2 bias = *(const float2*)((isA ? b1 : b2) + h0);
    __half* dst = isA ? g_a : g_b;
    int s0 = sg * 32 + rg * 4;

    float va[4], vb2[4];
    #pragma unroll
    for (int j = 0; j < 4; j++) {
        float mk = mask[(s0 + j) * R_DIM + r];
        va[j]  = (acc[j][0] + bias.x) * mk;
        vb2[j] = (acc[j][1] + bias.y) * mk;
    }
    size_t base0 = (size_t)(r * CH + h0) * S_DIM + s0;
    *(uint2*)&dst[base0]         = make_uint2(pack_h2(va[0], va[1]), pack_h2(va[2], va[3]));
    *(uint2*)&dst[base0 + S_DIM] = make_uint2(pack_h2(vb2[0], vb2[1]), pack_h2(vb2[2], vb2[3]));
}

// ---------------------------------------------------------------------------
// Kernel 1b: transpose+convert w_out [k][z] fp32 -> g_w [z][k] fp16
// ---------------------------------------------------------------------------
__global__ void k_wprep(const float* __restrict__ w_out)
{
    __shared__ float t[32][33];
    int tx = threadIdx.x, ty = threadIdx.y;
    int k0 = blockIdx.x * 32, z0 = blockIdx.y * 32;
    t[ty][tx] = w_out[(size_t)(k0 + ty) * CZ + z0 + tx];
    __syncthreads();
    g_w[(size_t)(z0 + ty) * 1024 + k0 + tx] = __float2half_rn(t[tx][ty]);
}

// ---------------------------------------------------------------------------
// One K-chunk (32 k) of fp16 HMMA on a 128x128 tile: 2 ksteps x 16 MMA.
// ---------------------------------------------------------------------------
__device__ __forceinline__ void mma_chunk32(
    const char* stage, int wm, int wn, int g, int tg, float acc[4][4][4])
{
    const uint32_t* sA = (const uint32_t*)(stage + OFF_A);
    const uint32_t* sB = (const uint32_t*)(stage + OFF_B);

    #pragma unroll
    for (int ks = 0; ks < 2; ks++) {
        int q0 = ks * 8 + tg;
        uint32_t ah[4][4], bh[4][2];
        #pragma unroll
        for (int mt = 0; mt < 4; mt++) {
            int r0 = (wm * 64 + mt * 16 + g) * RPAD;
            ah[mt][0] = sA[r0 + q0];
            ah[mt][1] = sA[r0 + 8 * RPAD + q0];
            ah[mt][2] = sA[r0 + q0 + 4];
            ah[mt][3] = sA[r0 + 8 * RPAD + q0 + 4];
        }
        #pragma unroll
        for (int nt = 0; nt < 4; nt++) {
            int rn = (wn * 32 + nt * 8 + g) * RPAD;
            bh[nt][0] = sB[rn + q0];
            bh[nt][1] = sB[rn + q0 + 4];
        }
        #pragma unroll
        for (int mt = 0; mt < 4; mt++)
            #pragma unroll
            for (int nt = 0; nt < 4; nt++)
                mma_f16(acc[mt][nt], ah[mt], bh[nt]);
    }
}

// ---------------------------------------------------------------------------
// Kernel 2: outer contraction via fp16 HMMA, 4-stage cp.async, K-chunk 32.
// ---------------------------------------------------------------------------
__global__ __launch_bounds__(256, 2) void k_gemm1_mma()
{
    extern __shared__ char smem[];
    uint32_t sb = smem_u32(smem);

    int tid = threadIdx.x, lane = tid & 31, warp = tid >> 5;
    int g = lane >> 2, tg = lane & 3;
    int wm = warp & 1, wn = warp >> 1;
    int m0 = blockIdx.x * 128, n0 = blockIdx.y * 128;

    const uint4* pa = (const uint4*)g_a;   // row = 16 uint4 (128 s fp16)
    const uint4* pb = (const uint4*)g_b;

    float acc[4][4][4];
    #pragma unroll
    for (int a = 0; a < 4; a++)
        #pragma unroll
        for (int b = 0; b < 4; b++)
            #pragma unroll
            for (int c = 0; c < 4; c++) acc[a][b][c] = 0.f;

    // copy helper indices: 512 cp16 per array per chunk; thread does idx, idx+256
    int i0 = tid, i1 = tid + 256;
    int r0c = i0 >> 2, q0c = i0 & 3;
    int r1c = i1 >> 2, q1c = i1 & 3;

    // prologue: prefetch chunks 0..2
    #pragma unroll
    for (int pc = 0; pc < NSTAGE - 1; pc++) {
        uint32_t st = sb + pc * ST_B;
        cp16(st + OFF_A + r0c * ROW_B + q0c * 16, pa + (size_t)(m0 + r0c) * 16 + pc * 4 + q0c);
        cp16(st + OFF_A + r1c * ROW_B + q1c * 16, pa + (size_t)(m0 + r1c) * 16 + pc * 4 + q1c);
        cp16(st + OFF_B + r0c * ROW_B + q0c * 16, pb + (size_t)(n0 + r0c) * 16 + pc * 4 + q0c);
        cp16(st + OFF_B + r1c * ROW_B + q1c * 16, pb + (size_t)(n0 + r1c) * 16 + pc * 4 + q1c);
        CP_COMMIT();
    }

    #pragma unroll
    for (int kc = 0; kc < 4; kc++) {
        CP_WAIT2();
        __syncthreads();
        int kp = kc + NSTAGE - 1;
        if (kp < 4) {
            uint32_t st = sb + (kp & 3) * ST_B;
            cp16(st + OFF_A + r0c * ROW_B + q0c * 16, pa + (size_t)(m0 + r0c) * 16 + kp * 4 + q0c);
            cp16(st + OFF_A + r1c * ROW_B + q1c * 16, pa + (size_t)(m0 + r1c) * 16 + kp * 4 + q1c);
            cp16(st + OFF_B + r0c * ROW_B + q0c * 16, pb + (size_t)(n0 + r0c) * 16 + kp * 4 + q0c);
            cp16(st + OFF_B + r1c * ROW_B + q1c * 16, pb + (size_t)(n0 + r1c) * 16 + kp * 4 + q1c);
        }
        CP_COMMIT();
        mma_chunk32(smem + (kc & 3) * ST_B, wm, wn, g, tg, acc);
    }

    // Epilogue: fp16 into [i][j][h][kk]
    uint32_t* o32 = (uint32_t*)g_o;
    #pragma unroll
    for (int mt = 0; mt < 4; mt++) {
        int mbase = m0 + wm * 64 + mt * 16 + g;
        #pragma unroll
        for (int nt = 0; nt < 4; nt++) {
            int n  = n0 + wn * 32 + nt * 8 + 2 * tg;
            int j  = n >> 5, kk = n & 31;
            #pragma unroll
            for (int hf = 0; hf < 2; hf++) {
                int mm = mbase + hf * 8;
                int i  = mm >> 5, h = mm & 31;
                float cx = acc[mt][nt][hf * 2 + 0];
                float cy = acc[mt][nt][hf * 2 + 1];
                size_t idx = (size_t)(i * R_DIM + j) * 512 + h * 16 + (kk >> 1);
                o32[idx] = pack_h2(cx, cy);
            }
        }
    }
}

// ---------------------------------------------------------------------------
// Kernel 3: output GEMM via fp16 HMMA + bias + mask-norm, 4-stage, K-chunk 32.
// ---------------------------------------------------------------------------
__global__ __launch_bounds__(256, 2) void k_gemm2_mma(
    const float* __restrict__ mask, const float* __restrict__ b_out,
    float* __restrict__ out)
{
    extern __shared__ char smem[];
    __shared__ float norms[128];
    uint32_t sb = smem_u32(smem);

    int tid = threadIdx.x, lane = tid & 31, warp = tid >> 5;
    int g = lane >> 2, tg = lane & 3;
    int wm = warp & 1, wn = warp >> 1;
    int p0 = blockIdx.x * 128;
    int i  = p0 >> 8;
    int j0 = p0 & 255;

    if (tid < 128) {
        float nacc = 0.f;
        #pragma unroll 4
        for (int s = 0; s < S_DIM; s++)
            nacc += mask[s * R_DIM + i] * mask[s * R_DIM + j0 + tid];
        norms[tid] = nacc;
    }

    const uint4* pa = (const uint4*)g_o;   // row = 128 uint4 (1024 fp16)
    const uint4* pb = (const uint4*)g_w;

    float acc[4][4][4];
    #pragma unroll
    for (int a = 0; a < 4; a++)
        #pragma unroll
        for (int b = 0; b < 4; b++)
            #pragma unroll
            for (int c = 0; c < 4; c++) acc[a][b][c] = 0.f;

    int i0 = tid, i1 = tid + 256;
    int r0c = i0 >> 2, q0c = i0 & 3;
    int r1c = i1 >> 2, q1c = i1 & 3;

    // prologue
    #pragma unroll
    for (int pc = 0; pc < NSTAGE - 1; pc++) {
        uint32_t st = sb + pc * ST_B;
        cp16(st + OFF_A + r0c * ROW_B + q0c * 16, pa + (size_t)(p0 + r0c) * 128 + pc * 4 + q0c);
        cp16(st + OFF_A + r1c * ROW_B + q1c * 16, pa + (size_t)(p0 + r1c) * 128 + pc * 4 + q1c);
        cp16(st + OFF_B + r0c * ROW_B + q0c * 16, pb + (size_t)r0c * 128 + pc * 4 + q0c);
        cp16(st + OFF_B + r1c * ROW_B + q1c * 16, pb + (size_t)r1c * 128 + pc * 4 + q1c);
        CP_COMMIT();
    }

    for (int kc = 0; kc < 32; kc++) {
        CP_WAIT2();
        __syncthreads();
        int kp = kc + NSTAGE - 1;
        if (kp < 32) {
            uint32_t st = sb + (kp & 3) * ST_B;
            cp16(st + OFF_A + r0c * ROW_B + q0c * 16, pa + (size_t)(p0 + r0c) * 128 + kp * 4 + q0c);
            cp16(st + OFF_A + r1c * ROW_B + q1c * 16, pa + (size_t)(p0 + r1c) * 128 + kp * 4 + q1c);
            cp16(st + OFF_B + r0c * ROW_B + q0c * 16, pb + (size_t)r0c * 128 + kp * 4 + q0c);
            cp16(st + OFF_B + r1c * ROW_B + q1c * 16, pb + (size_t)r1c * 128 + kp * 4 + q1c);
        }
        CP_COMMIT();
        mma_chunk32(smem + (kc & 3) * ST_B, wm, wn, g, tg, acc);
    }

    // Epilogue: bias + norm divide, fp32 out
    #pragma unroll
    for (int mt = 0; mt < 4; mt++) {
        int pl = wm * 64 + mt * 16 + g;
        #pragma unroll
        for (int nt = 0; nt < 4; nt++) {
            int z = wn * 32 + nt * 8 + 2 * tg;
            float2 bz = *(const float2*)&b_out[z];
            #pragma unroll
            for (int hf = 0; hf < 2; hf++) {
                int pp = pl + hf * 8;
                float inv = 1.0f / (MASK_EPS + norms[pp]);
                float cx = (acc[mt][nt][hf * 2 + 0] + bz.x) * inv;
                float cy = (acc[mt][nt][hf * 2 + 1] + bz.y) * inv;
                *(float2*)&out[(size_t)(p0 + pp) * CZ + z] = make_float2(cx, cy);
            }
        }
    }
}

// ---------------------------------------------------------------------------
extern "C" void kernel_launch(void* const* d_in, const int* in_sizes, int n_in,
                              void* d_out, int out_size)
{
    const float* m     = (const float*)d_in[0];
    const float* mask  = (const float*)d_in[1];
    const float* lnw   = (const float*)d_in[2];
    const float* lnb   = (const float*)d_in[3];
    const float* w1    = (const float*)d_in[4];
    const float* b1    = (const float*)d_in[5];
    const float* w2    = (const float*)d_in[6];
    const float* b2    = (const float*)d_in[7];
    const float* w_out = (const float*)d_in[8];
    const float* b_out = (const float*)d_in[9];
    float* out = (float*)d_out;

    static int attr_done = 0;
    if (!attr_done) {
        cudaFuncSetAttribute(k_gemm1_mma,
            cudaFuncAttributeMaxDynamicSharedMemorySize, SMEM_PIPE);
        cudaFuncSetAttribute(k_gemm2_mma,
            cudaFuncAttributeMaxDynamicSharedMemorySize, SMEM_PIPE);
        attr_done = 1;
    }

    k_wprep<<<dim3(32, 4), dim3(32, 32)>>>(w_out);
    k_proj<<<1024, 256>>>(m, mask, lnw, lnb, w1, b1, w2, b2);
    k_gemm1_mma<<<dim3(64, 64), 256, SMEM_PIPE>>>();
    k_gemm2_mma<<<512, 256, SMEM_PIPE>>>(mask, b_out, out);
}